// round 7
// baseline (speedup 1.0000x reference)
#include <cuda_runtime.h>
#include <math.h>

#define BATCH 512
#define MSIZE 4096
#define DDIM  64
#define CDIM  256
#define EPSF  1e-8f
#define NTHREADS 256
#define NWARPS  (NTHREADS / 32)

__device__ __forceinline__ float block_reduce_sum(float v, float* sbuf, int t) {
    #pragma unroll
    for (int o = 16; o > 0; o >>= 1) v += __shfl_xor_sync(0xffffffffu, v, o);
    if ((t & 31) == 0) sbuf[t >> 5] = v;
    __syncthreads();
    if (t < NWARPS) {
        float x = sbuf[t];
        #pragma unroll
        for (int o = NWARPS / 2; o > 0; o >>= 1) x += __shfl_xor_sync(0xffu, x, o);
        if (t == 0) sbuf[0] = x;
    }
    __syncthreads();
    float r = sbuf[0];
    __syncthreads();
    return r;
}

__device__ __forceinline__ float softplusf(float x) {
    return (x > 20.0f) ? x : log1pf(expf(x));
}

__device__ __forceinline__ float dot4(float4 a, float4 b) {
    return a.x*b.x + a.y*b.y + a.z*b.z + a.w*b.w;
}

// Load 4 rows (r, r+32, r+64, r+96), 2 float4 per row for this lane.
#define LOADROWS(buf, rbase)                                             \
    {                                                                    \
        const float4* _p = mem4 + (size_t)(rbase) * 16;                  \
        buf[0] = __ldcs(_p);            buf[1] = __ldcs(_p + 8);         \
        buf[2] = __ldcs(_p + 32 * 16);  buf[3] = __ldcs(_p + 32 * 16 + 8);\
        buf[4] = __ldcs(_p + 64 * 16);  buf[5] = __ldcs(_p + 64 * 16 + 8);\
        buf[6] = __ldcs(_p + 96 * 16);  buf[7] = __ldcs(_p + 96 * 16 + 8);\
    }

// Dot + norm for 4 rows, 8-lane shuffle reduce, lane-0 store to s_sim.
#define COMPUTE(buf, rbase)                                              \
    {                                                                    \
        float d0 = dot4(buf[0], bqa) + dot4(buf[1], bqb);                \
        float n0 = dot4(buf[0], buf[0]) + dot4(buf[1], buf[1]);          \
        float d1 = dot4(buf[2], bqa) + dot4(buf[3], bqb);                \
        float n1 = dot4(buf[2], buf[2]) + dot4(buf[3], buf[3]);          \
        float d2 = dot4(buf[4], bqa) + dot4(buf[5], bqb);                \
        float n2 = dot4(buf[4], buf[4]) + dot4(buf[5], buf[5]);          \
        float d3 = dot4(buf[6], bqa) + dot4(buf[7], bqb);                \
        float n3 = dot4(buf[6], buf[6]) + dot4(buf[7], buf[7]);          \
        _Pragma("unroll")                                                \
        for (int o = 4; o > 0; o >>= 1) {                                \
            d0 += __shfl_xor_sync(0xffffffffu, d0, o);                   \
            n0 += __shfl_xor_sync(0xffffffffu, n0, o);                   \
            d1 += __shfl_xor_sync(0xffffffffu, d1, o);                   \
            n1 += __shfl_xor_sync(0xffffffffu, n1, o);                   \
            d2 += __shfl_xor_sync(0xffffffffu, d2, o);                   \
            n2 += __shfl_xor_sync(0xffffffffu, n2, o);                   \
            d3 += __shfl_xor_sync(0xffffffffu, d3, o);                   \
            n3 += __shfl_xor_sync(0xffffffffu, n3, o);                   \
        }                                                                \
        if (h == 0) {                                                    \
            s_sim[(rbase)     ] = d0 * rsqrtf(n0 + 1e-16f);              \
            s_sim[(rbase) + 32] = d1 * rsqrtf(n1 + 1e-16f);              \
            s_sim[(rbase) + 64] = d2 * rsqrtf(n2 + 1e-16f);              \
            s_sim[(rbase) + 96] = d3 * rsqrtf(n3 + 1e-16f);              \
        }                                                                \
    }

__global__ __launch_bounds__(NTHREADS, 3)
void ntm_head_kernel(const float* __restrict__ memory,
                     const float* __restrict__ cs_all,
                     const float* __restrict__ prev,
                     const float* __restrict__ Wk,
                     const float* __restrict__ Wb,    const float* __restrict__ bb,
                     const float* __restrict__ Wgate, const float* __restrict__ bgate,
                     const float* __restrict__ Ws,    const float* __restrict__ bs,
                     const float* __restrict__ Wg,    const float* __restrict__ bg,
                     float* __restrict__ out)
{
    __shared__ float s_cs[CDIM];
    __shared__ __align__(16) float s_q[DDIM];
    __shared__ float s_red[NWARPS];
    __shared__ float s_sim[MSIZE];
    __shared__ float s_g[MSIZE];

    const int b = blockIdx.x;
    const int t = threadIdx.x;

    // ---------------- Phase 0: load controller state ----------------
    s_cs[t] = cs_all[(size_t)b * CDIM + t];
    __syncthreads();

    // ---------------- Phase 1: small dots ----------------------------
    const float csv = s_cs[t];
    float zb    = block_reduce_sum(csv * Wb[t],         s_red, t);
    float zgate = block_reduce_sum(csv * Wgate[t],      s_red, t);
    float zG    = block_reduce_sum(csv * Wg[t],         s_red, t);
    float z0    = block_reduce_sum(csv * Ws[t * 3 + 0], s_red, t);
    float z1    = block_reduce_sum(csv * Ws[t * 3 + 1], s_red, t);
    float z2    = block_reduce_sum(csv * Ws[t * 3 + 2], s_red, t);

    const float beta  = softplusf(zb + bb[0]) + 1.0f;
    const float gate  = 1.0f / (1.0f + __expf(-(zgate + bgate[0])));
    const float gamma = softplusf(zG + bg[0]) + 1.0f;
    z0 += bs[0]; z1 += bs[1]; z2 += bs[2];
    {
        float zm = fmaxf(z0, fmaxf(z1, z2));
        z0 = __expf(z0 - zm); z1 = __expf(z1 - zm); z2 = __expf(z2 - zm);
        float iz = 1.0f / (z0 + z1 + z2);
        z0 *= iz; z1 *= iz; z2 *= iz;
    }

    // ---------------- Phase 1b: query = cs @ Wk, fold beta/norm -------
    if (t < DDIM) {
        float acc = 0.0f;
        #pragma unroll 8
        for (int c = 0; c < CDIM; c++) acc = fmaf(s_cs[c], Wk[c * DDIM + t], acc);
        s_q[t] = acc;
    }
    float lq = (t < DDIM) ? s_q[t] * s_q[t] : 0.0f;
    float qn2 = block_reduce_sum(lq, s_red, t);
    const float qscale = beta / (sqrtf(qn2) + EPSF);
    if (t < DDIM) s_q[t] *= qscale;
    __syncthreads();

    // ---------------- Phase 2: sim over M — software-pipelined --------
    // 8 lanes/row, 4 rows per warp per chunk, 128 rows per chunk,
    // double-buffered prefetch: loads for chunk i+1 are in flight while
    // computing chunk i, keeping ~1KB/warp continuously outstanding.
    {
        const int lane = t & 31;
        const int sr   = lane >> 3;       // 0..3 : row within warp quad
        const int h    = lane & 7;        // 0..7 : float4 slot in half-row
        const int rb   = (t >> 5) * 4 + sr; // wid*4+sr  in [0,32)
        const float4* q4 = (const float4*)s_q;
        const float4 bqa = q4[h];
        const float4 bqb = q4[h + 8];
        const float4* mem4 = (const float4*)memory + (size_t)b * MSIZE * 16 + h;

        float4 A[8], B[8];
        LOADROWS(A, rb);                         // chunk 0
        #pragma unroll 1
        for (int it = 0; it < MSIZE; it += 256) {
            LOADROWS(B, it + 128 + rb);          // prefetch odd chunk
            COMPUTE(A, it + rb);                 // compute even chunk
            if (it + 256 < MSIZE)
                LOADROWS(A, it + 256 + rb);      // prefetch next even
            COMPUTE(B, it + 128 + rb);           // compute odd chunk
        }
    }
    __syncthreads();

    // ---------------- Phase 3: softmax over M (no max pass needed:
    // |beta*sim| <= beta ~ small, exp is safe) -------------------------
    float ls = 0.0f;
    for (int j = t; j < MSIZE; j += NTHREADS) {
        float e = __expf(s_sim[j]);
        s_sim[j] = e;
        ls += e;
    }
    const float Z = block_reduce_sum(ls, s_red, t);

    // ---------------- Phase 4: gate blend with previous weights -------
    const float invZg = gate / Z;
    const float og = 1.0f - gate;
    const float* prow = prev + (size_t)b * MSIZE;
    for (int j = t; j < MSIZE; j += NTHREADS)
        s_g[j] = s_sim[j] * invZg + og * __ldcs(&prow[j]);
    __syncthreads();

    // ---------------- Phase 5: circular conv + sharpen ----------------
    float lp = 0.0f;
    for (int j = t; j < MSIZE; j += NTHREADS) {
        float sh = s_g[(j - 1) & (MSIZE - 1)] * z0
                 + s_g[j]                     * z1
                 + s_g[(j + 1) & (MSIZE - 1)] * z2;
        float p = __powf(sh + EPSF, gamma);
        s_sim[j] = p;
        lp += p;
    }
    const float P = block_reduce_sum(lp, s_red, t);

    // ---------------- Phase 6: final normalize + store ----------------
    const float inv = 1.0f / (P + EPSF);
    float* orow = out + (size_t)b * MSIZE;
    for (int j = t; j < MSIZE; j += NTHREADS) __stcs(&orow[j], s_sim[j] * inv);
}

extern "C" void kernel_launch(void* const* d_in, const int* in_sizes, int n_in,
                              void* d_out, int out_size) {
    const float* memory = (const float*)d_in[0];
    const float* cs     = (const float*)d_in[1];
    const float* prev   = (const float*)d_in[2];
    const float* Wk     = (const float*)d_in[3];
    const float* Wb     = (const float*)d_in[4];
    const float* bb     = (const float*)d_in[5];
    const float* Wgate  = (const float*)d_in[6];
    const float* bgate  = (const float*)d_in[7];
    const float* Ws     = (const float*)d_in[8];
    const float* bs     = (const float*)d_in[9];
    const float* Wg     = (const float*)d_in[10];
    const float* bg     = (const float*)d_in[11];
    float* out = (float*)d_out;

    ntm_head_kernel<<<BATCH, NTHREADS>>>(memory, cs, prev, Wk, Wb, bb,
                                         Wgate, bgate, Ws, bs, Wg, bg, out);
}

// round 10
// speedup vs baseline: 1.4614x; 1.4614x over previous
#include <cuda_runtime.h>
#include <math.h>

#define BATCH    512
#define MSIZE    4096
#define DDIM     64
#define CDIM     256
#define EPSF     1e-8f
#define NTHREADS 256

struct Params { float z0, z1, z2, gate, gamma; };

__device__ __forceinline__ void named_bar(int id, int count) {
    asm volatile("bar.sync %0, %1;" :: "r"(id), "r"(count) : "memory");
}

// Full-block (256-thread) reduce for the prologue.
__device__ __forceinline__ float block_reduce_sum(float v, float* sbuf, int t) {
    #pragma unroll
    for (int o = 16; o > 0; o >>= 1) v += __shfl_xor_sync(0xffffffffu, v, o);
    if ((t & 31) == 0) sbuf[t >> 5] = v;
    __syncthreads();
    float r = 0.0f;
    #pragma unroll
    for (int i = 0; i < 8; i++) r += sbuf[i];
    __syncthreads();
    return r;
}

// Group reduce over GSIZE threads using named barrier `barid`.
template<int GSIZE>
__device__ __forceinline__ float group_reduce_sum(float v, float* sbuf, int gt, int barid) {
    #pragma unroll
    for (int o = 16; o > 0; o >>= 1) v += __shfl_xor_sync(0xffffffffu, v, o);
    if ((gt & 31) == 0) sbuf[gt >> 5] = v;
    named_bar(barid, GSIZE);
    float r = 0.0f;
    #pragma unroll
    for (int i = 0; i < GSIZE / 32; i++) r += sbuf[i];
    named_bar(barid, GSIZE);
    return r;
}

__device__ __forceinline__ float softplusf(float x) {
    return (x > 20.0f) ? x : log1pf(expf(x));
}

__device__ __forceinline__ float dot4(float4 a, float4 b) {
    return a.x*b.x + a.y*b.y + a.z*b.z + a.w*b.w;
}

// Stream sim for one batch using NW warps (warp-local id wl in [0,NW)).
// R3-proven access pattern: 8 lanes/row, 4 rows per warp per iteration.
template<int NW>
__device__ void stream_sim(const float4* __restrict__ memrow,  // batch base (float4 units)
                           const float* __restrict__ s_qv,     // beta-folded query
                           float* __restrict__ s_sim,
                           int wl, int lane)
{
    const int sr = (lane >> 3) & 3;
    const int h  = lane & 7;
    const int rb = wl * 4 + sr;
    constexpr int SP   = NW * 4;    // spacing between the 4 row-quads
    constexpr int STEP = NW * 16;   // rows covered per iteration

    const float4* q4 = (const float4*)s_qv;
    const float4 bqa = q4[h];
    const float4 bqb = q4[h + 8];
    const float4* mem4 = memrow + h;

    #pragma unroll 1
    for (int it = 0; it < MSIZE; it += STEP) {
        const int r0 = it + rb;
        const float4* p0 = mem4 + (size_t)(r0         ) * 16;
        const float4* p1 = mem4 + (size_t)(r0 +     SP) * 16;
        const float4* p2 = mem4 + (size_t)(r0 + 2 * SP) * 16;
        const float4* p3 = mem4 + (size_t)(r0 + 3 * SP) * 16;

        float4 a0 = __ldcs(p0), a1 = __ldcs(p0 + 8);
        float4 b0 = __ldcs(p1), b1 = __ldcs(p1 + 8);
        float4 c0 = __ldcs(p2), c1 = __ldcs(p2 + 8);
        float4 e0 = __ldcs(p3), e1 = __ldcs(p3 + 8);

        float d0 = dot4(a0, bqa) + dot4(a1, bqb);
        float n0 = dot4(a0, a0)  + dot4(a1, a1);
        float d1 = dot4(b0, bqa) + dot4(b1, bqb);
        float n1 = dot4(b0, b0)  + dot4(b1, b1);
        float d2 = dot4(c0, bqa) + dot4(c1, bqb);
        float n2 = dot4(c0, c0)  + dot4(c1, c1);
        float d3 = dot4(e0, bqa) + dot4(e1, bqb);
        float n3 = dot4(e0, e0)  + dot4(e1, e1);

        #pragma unroll
        for (int o = 4; o > 0; o >>= 1) {
            d0 += __shfl_xor_sync(0xffffffffu, d0, o);
            n0 += __shfl_xor_sync(0xffffffffu, n0, o);
            d1 += __shfl_xor_sync(0xffffffffu, d1, o);
            n1 += __shfl_xor_sync(0xffffffffu, n1, o);
            d2 += __shfl_xor_sync(0xffffffffu, d2, o);
            n2 += __shfl_xor_sync(0xffffffffu, n2, o);
            d3 += __shfl_xor_sync(0xffffffffu, d3, o);
            n3 += __shfl_xor_sync(0xffffffffu, n3, o);
        }
        if (h == 0) {
            s_sim[r0         ] = d0 * rsqrtf(n0 + 1e-16f);
            s_sim[r0 +     SP] = d1 * rsqrtf(n1 + 1e-16f);
            s_sim[r0 + 2 * SP] = d2 * rsqrtf(n2 + 1e-16f);
            s_sim[r0 + 3 * SP] = d3 * rsqrtf(n3 + 1e-16f);
        }
    }
}

// Epilogue: softmax (no max pass; |beta*sim|<=beta is small) -> gate blend
// (in-place into s_sim) -> circular conv + pow (p staged in registers) ->
// normalize -> store. Runs on GSIZE threads with named barrier `barid`.
template<int GSIZE>
__device__ void epilogue(float* __restrict__ s_sim,
                         const float* __restrict__ prow,
                         float* __restrict__ orow,
                         const Params P, float* redbuf, int gt, int barid)
{
    constexpr int K = MSIZE / GSIZE;

    float ls = 0.0f;
    #pragma unroll
    for (int k = 0; k < K; k++) {
        int j = gt + k * GSIZE;
        float e = __expf(s_sim[j]);
        s_sim[j] = e;
        ls += e;
    }
    const float Z = group_reduce_sum<GSIZE>(ls, redbuf, gt, barid);

    const float invZg = P.gate / Z;
    const float og    = 1.0f - P.gate;
    #pragma unroll
    for (int k = 0; k < K; k++) {
        int j = gt + k * GSIZE;
        s_sim[j] = s_sim[j] * invZg + og * __ldcs(&prow[j]);   // g in place
    }
    named_bar(barid, GSIZE);   // all g visible before neighbor reads

    float p[K];
    float lp = 0.0f;
    #pragma unroll
    for (int k = 0; k < K; k++) {
        int j = gt + k * GSIZE;
        float sh = s_sim[(j - 1) & (MSIZE - 1)] * P.z0
                 + s_sim[j]                     * P.z1
                 + s_sim[(j + 1) & (MSIZE - 1)] * P.z2;
        p[k] = __powf(sh + EPSF, P.gamma);
        lp += p[k];
    }
    const float Psum = group_reduce_sum<GSIZE>(lp, redbuf, gt, barid);

    const float inv = 1.0f / (Psum + EPSF);
    #pragma unroll
    for (int k = 0; k < K; k++) {
        int j = gt + k * GSIZE;
        __stcs(&orow[j], p[k] * inv);
    }
}

__global__ __launch_bounds__(NTHREADS, 2)
void ntm_head_kernel(const float* __restrict__ memory,
                     const float* __restrict__ cs_all,
                     const float* __restrict__ prev,
                     const float* __restrict__ Wk,
                     const float* __restrict__ Wb,    const float* __restrict__ bb,
                     const float* __restrict__ Wgate, const float* __restrict__ bgate,
                     const float* __restrict__ Ws,    const float* __restrict__ bs,
                     const float* __restrict__ Wg,    const float* __restrict__ bg,
                     float* __restrict__ out)
{
    __shared__ float s_sim0[MSIZE];
    __shared__ float s_sim1[MSIZE];
    __shared__ float s_cs[CDIM];
    __shared__ __align__(16) float s_q[2][DDIM];
    __shared__ Params s_par[2];
    __shared__ float s_red8[8];   // prologue reduces (256 threads)
    __shared__ float s_redA[4];   // group-A epilogue reduces (128 threads)
    __shared__ float s_redF[8];   // final epilogue reduces (256 threads)

    const int t    = threadIdx.x;
    const int wid  = t >> 5;
    const int lane = t & 31;
    const int b0   = blockIdx.x * 2;

    // =========== Prologue for both batches (all 256 threads) ==========
    for (int s = 0; s < 2; s++) {
        const int b = b0 + s;
        s_cs[t] = cs_all[(size_t)b * CDIM + t];
        __syncthreads();

        const float csv = s_cs[t];
        float zb    = block_reduce_sum(csv * Wb[t],         s_red8, t);
        float zgate = block_reduce_sum(csv * Wgate[t],      s_red8, t);
        float zG    = block_reduce_sum(csv * Wg[t],         s_red8, t);
        float z0    = block_reduce_sum(csv * Ws[t * 3 + 0], s_red8, t);
        float z1    = block_reduce_sum(csv * Ws[t * 3 + 1], s_red8, t);
        float z2    = block_reduce_sum(csv * Ws[t * 3 + 2], s_red8, t);

        const float beta  = softplusf(zb + bb[0]) + 1.0f;
        const float gate  = 1.0f / (1.0f + __expf(-(zgate + bgate[0])));
        const float gamma = softplusf(zG + bg[0]) + 1.0f;
        z0 += bs[0]; z1 += bs[1]; z2 += bs[2];
        {
            float zm = fmaxf(z0, fmaxf(z1, z2));
            z0 = __expf(z0 - zm); z1 = __expf(z1 - zm); z2 = __expf(z2 - zm);
            float iz = 1.0f / (z0 + z1 + z2);
            z0 *= iz; z1 *= iz; z2 *= iz;
        }

        if (t < DDIM) {
            float acc = 0.0f;
            #pragma unroll 8
            for (int c = 0; c < CDIM; c++) acc = fmaf(s_cs[c], Wk[c * DDIM + t], acc);
            s_q[s][t] = acc;
        }
        float lq = (t < DDIM) ? s_q[s][t] * s_q[s][t] : 0.0f;
        float qn2 = block_reduce_sum(lq, s_red8, t);
        const float qscale = beta / (sqrtf(qn2) + EPSF);
        if (t < DDIM) s_q[s][t] *= qscale;

        if (t == 0) {
            s_par[s].z0 = z0; s_par[s].z1 = z1; s_par[s].z2 = z2;
            s_par[s].gate = gate; s_par[s].gamma = gamma;
        }
        __syncthreads();   // protect s_cs reuse + publish s_par/s_q
    }

    const float4* mem0 = (const float4*)memory + (size_t)b0 * MSIZE * 16;
    const float4* mem1 = mem0 + (size_t)MSIZE * 16;

    // =========== Stage 0: stream b0 with all 8 warps ==================
    stream_sim<8>(mem0, s_q[0], s_sim0, wid, lane);
    __syncthreads();

    // =========== Stage 1: epilogue(b0) on warps 0-3 | stream b1 on 4-7
    if (t < 128) {
        Params P0 = s_par[0];
        epilogue<128>(s_sim0, prev + (size_t)b0 * MSIZE,
                      out + (size_t)b0 * MSIZE, P0, s_redA, t, 1);
    } else {
        stream_sim<4>(mem1, s_q[1], s_sim1, wid - 4, lane);
    }
    __syncthreads();

    // =========== Stage 2: epilogue(b1) on all 8 warps =================
    {
        Params P1 = s_par[1];
        epilogue<256>(s_sim1, prev + (size_t)(b0 + 1) * MSIZE,
                      out + (size_t)(b0 + 1) * MSIZE, P1, s_redF, t, 0);
    }
}

extern "C" void kernel_launch(void* const* d_in, const int* in_sizes, int n_in,
                              void* d_out, int out_size) {
    const float* memory = (const float*)d_in[0];
    const float* cs     = (const float*)d_in[1];
    const float* prev   = (const float*)d_in[2];
    const float* Wk     = (const float*)d_in[3];
    const float* Wb     = (const float*)d_in[4];
    const float* bb     = (const float*)d_in[5];
    const float* Wgate  = (const float*)d_in[6];
    const float* bgate  = (const float*)d_in[7];
    const float* Ws     = (const float*)d_in[8];
    const float* bs     = (const float*)d_in[9];
    const float* Wg     = (const float*)d_in[10];
    const float* bg     = (const float*)d_in[11];
    float* out = (float*)d_out;

    ntm_head_kernel<<<BATCH / 2, NTHREADS>>>(memory, cs, prev, Wk, Wb, bb,
                                             Wgate, bgate, Ws, bs, Wg, bg, out);
}

// round 12
// speedup vs baseline: 1.6780x; 1.1482x over previous
#include <cuda_runtime.h>
#include <math.h>

#define BATCH    512
#define MSIZE    4096
#define DDIM     64
#define CDIM     256
#define EPSF     1e-8f
#define NTHREADS 256

struct Params { float z0, z1, z2, gate, gamma; };

__device__ __forceinline__ void named_bar(int id, int count) {
    asm volatile("bar.sync %0, %1;" :: "r"(id), "r"(count) : "memory");
}

// Full-block (256-thread) reduce for the prologue.
__device__ __forceinline__ float block_reduce_sum(float v, float* sbuf, int t) {
    #pragma unroll
    for (int o = 16; o > 0; o >>= 1) v += __shfl_xor_sync(0xffffffffu, v, o);
    if ((t & 31) == 0) sbuf[t >> 5] = v;
    __syncthreads();
    float r = 0.0f;
    #pragma unroll
    for (int i = 0; i < 8; i++) r += sbuf[i];
    __syncthreads();
    return r;
}

// Group reduce over GSIZE threads using named barrier `barid`.
template<int GSIZE>
__device__ __forceinline__ float group_reduce_sum(float v, float* sbuf, int gt, int barid) {
    #pragma unroll
    for (int o = 16; o > 0; o >>= 1) v += __shfl_xor_sync(0xffffffffu, v, o);
    if ((gt & 31) == 0) sbuf[gt >> 5] = v;
    named_bar(barid, GSIZE);
    float r = 0.0f;
    #pragma unroll
    for (int i = 0; i < GSIZE / 32; i++) r += sbuf[i];
    named_bar(barid, GSIZE);
    return r;
}

__device__ __forceinline__ float softplusf(float x) {
    return (x > 20.0f) ? x : log1pf(expf(x));
}

__device__ __forceinline__ float dot4(float4 a, float4 b) {
    return a.x*b.x + a.y*b.y + a.z*b.z + a.w*b.w;
}

// Stream sim for one batch with NW warps. 8 lanes/row; 8 rows per warp per
// iteration => a single burst of 16 independent LDG.128 (2KB) per warp kept
// in flight before any consumption, then one 3-step shuffle reduce.
template<int NW>
__device__ void stream_sim(const float4* __restrict__ memrow,  // batch base (float4 units)
                           const float* __restrict__ s_qv,     // beta-folded query
                           float* __restrict__ s_sim,
                           int wl, int lane)
{
    const int sr = (lane >> 3) & 3;
    const int h  = lane & 7;
    const int rb = wl * 4 + sr;
    constexpr int SP   = NW * 4;    // spacing between row-quads
    constexpr int STEP = NW * 32;   // rows covered per iteration (8 quads)

    const float4* q4 = (const float4*)s_qv;
    const float4 bqa = q4[h];
    const float4 bqb = q4[h + 8];
    const float4* mem4 = memrow + h;

    float4 buf[16];
    float d[8], n[8];

    #pragma unroll 1
    for (int it = 0; it < MSIZE; it += STEP) {
        const int r0 = it + rb;

        #pragma unroll
        for (int q = 0; q < 8; q++) {
            const float4* p = mem4 + (size_t)(r0 + q * SP) * 16;
            buf[2 * q]     = __ldcs(p);
            buf[2 * q + 1] = __ldcs(p + 8);
        }

        #pragma unroll
        for (int q = 0; q < 8; q++) {
            float4 a = buf[2 * q], c = buf[2 * q + 1];
            d[q] = dot4(a, bqa) + dot4(c, bqb);
            n[q] = dot4(a, a)   + dot4(c, c);
        }

        #pragma unroll
        for (int o = 4; o > 0; o >>= 1) {
            #pragma unroll
            for (int q = 0; q < 8; q++) {
                d[q] += __shfl_xor_sync(0xffffffffu, d[q], o);
                n[q] += __shfl_xor_sync(0xffffffffu, n[q], o);
            }
        }
        if (h == 0) {
            #pragma unroll
            for (int q = 0; q < 8; q++)
                s_sim[r0 + q * SP] = d[q] * rsqrtf(n[q] + 1e-16f);
        }
    }
}

// Epilogue: softmax (no max pass; |beta*sim|<=beta is small) -> gate blend
// (in-place) -> circular conv + pow (p staged in registers) -> normalize.
template<int GSIZE>
__device__ void epilogue(float* __restrict__ s_sim,
                         const float* __restrict__ prow,
                         float* __restrict__ orow,
                         const Params P, float* redbuf, int gt, int barid)
{
    constexpr int K = MSIZE / GSIZE;

    float ls = 0.0f;
    #pragma unroll
    for (int k = 0; k < K; k++) {
        int j = gt + k * GSIZE;
        float e = __expf(s_sim[j]);
        s_sim[j] = e;
        ls += e;
    }
    const float Z = group_reduce_sum<GSIZE>(ls, redbuf, gt, barid);

    const float invZg = P.gate / Z;
    const float og    = 1.0f - P.gate;
    #pragma unroll
    for (int k = 0; k < K; k++) {
        int j = gt + k * GSIZE;
        s_sim[j] = s_sim[j] * invZg + og * __ldcs(&prow[j]);   // g in place
    }
    named_bar(barid, GSIZE);   // all g visible before neighbor reads

    float p[K];
    float lp = 0.0f;
    #pragma unroll
    for (int k = 0; k < K; k++) {
        int j = gt + k * GSIZE;
        float sh = s_sim[(j - 1) & (MSIZE - 1)] * P.z0
                 + s_sim[j]                     * P.z1
                 + s_sim[(j + 1) & (MSIZE - 1)] * P.z2;
        p[k] = __powf(sh + EPSF, P.gamma);
        lp += p[k];
    }
    const float Psum = group_reduce_sum<GSIZE>(lp, redbuf, gt, barid);

    const float inv = 1.0f / (Psum + EPSF);
    #pragma unroll
    for (int k = 0; k < K; k++) {
        int j = gt + k * GSIZE;
        __stcs(&orow[j], p[k] * inv);
    }
}

__global__ __launch_bounds__(NTHREADS, 2)
void ntm_head_kernel(const float* __restrict__ memory,
                     const float* __restrict__ cs_all,
                     const float* __restrict__ prev,
                     const float* __restrict__ Wk,
                     const float* __restrict__ Wb,    const float* __restrict__ bb,
                     const float* __restrict__ Wgate, const float* __restrict__ bgate,
                     const float* __restrict__ Ws,    const float* __restrict__ bs,
                     const float* __restrict__ Wg,    const float* __restrict__ bg,
                     float* __restrict__ out)
{
    __shared__ float s_sim0[MSIZE];
    __shared__ float s_sim1[MSIZE];
    __shared__ float s_cs[CDIM];
    __shared__ __align__(16) float s_q[2][DDIM];
    __shared__ Params s_par[2];
    __shared__ float s_red8[8];   // prologue reduces (256 threads)
    __shared__ float s_redA[4];   // group-A epilogue reduces (128 threads)
    __shared__ float s_redF[8];   // final epilogue reduces (256 threads)

    const int t    = threadIdx.x;
    const int wid  = t >> 5;
    const int lane = t & 31;
    const int b0   = blockIdx.x * 2;

    // =========== Prologue for both batches (all 256 threads) ==========
    for (int s = 0; s < 2; s++) {
        const int b = b0 + s;
        s_cs[t] = cs_all[(size_t)b * CDIM + t];
        __syncthreads();

        const float csv = s_cs[t];
        float zb    = block_reduce_sum(csv * Wb[t],         s_red8, t);
        float zgate = block_reduce_sum(csv * Wgate[t],      s_red8, t);
        float zG    = block_reduce_sum(csv * Wg[t],         s_red8, t);
        float z0    = block_reduce_sum(csv * Ws[t * 3 + 0], s_red8, t);
        float z1    = block_reduce_sum(csv * Ws[t * 3 + 1], s_red8, t);
        float z2    = block_reduce_sum(csv * Ws[t * 3 + 2], s_red8, t);

        const float beta  = softplusf(zb + bb[0]) + 1.0f;
        const float gate  = 1.0f / (1.0f + __expf(-(zgate + bgate[0])));
        const float gamma = softplusf(zG + bg[0]) + 1.0f;
        z0 += bs[0]; z1 += bs[1]; z2 += bs[2];
        {
            float zm = fmaxf(z0, fmaxf(z1, z2));
            z0 = __expf(z0 - zm); z1 = __expf(z1 - zm); z2 = __expf(z2 - zm);
            float iz = 1.0f / (z0 + z1 + z2);
            z0 *= iz; z1 *= iz; z2 *= iz;
        }

        if (t < DDIM) {
            float acc = 0.0f;
            #pragma unroll 8
            for (int c = 0; c < CDIM; c++) acc = fmaf(s_cs[c], Wk[c * DDIM + t], acc);
            s_q[s][t] = acc;
        }
        float lq = (t < DDIM) ? s_q[s][t] * s_q[s][t] : 0.0f;
        float qn2 = block_reduce_sum(lq, s_red8, t);
        const float qscale = beta / (sqrtf(qn2) + EPSF);
        if (t < DDIM) s_q[s][t] *= qscale;

        if (t == 0) {
            s_par[s].z0 = z0; s_par[s].z1 = z1; s_par[s].z2 = z2;
            s_par[s].gate = gate; s_par[s].gamma = gamma;
        }
        __syncthreads();   // protect s_cs reuse + publish s_par/s_q
    }

    const float4* mem0 = (const float4*)memory + (size_t)b0 * MSIZE * 16;
    const float4* mem1 = mem0 + (size_t)MSIZE * 16;

    // =========== Stage 0: stream b0 with all 8 warps ==================
    stream_sim<8>(mem0, s_q[0], s_sim0, wid, lane);
    __syncthreads();

    // =========== Stage 1: epilogue(b0) on warps 0-3 | stream b1 on 4-7
    if (t < 128) {
        Params P0 = s_par[0];
        epilogue<128>(s_sim0, prev + (size_t)b0 * MSIZE,
                      out + (size_t)b0 * MSIZE, P0, s_redA, t, 1);
    } else {
        stream_sim<4>(mem1, s_q[1], s_sim1, wid - 4, lane);
    }
    __syncthreads();

    // =========== Stage 2: epilogue(b1) on all 8 warps =================
    {
        Params P1 = s_par[1];
        epilogue<256>(s_sim1, prev + (size_t)(b0 + 1) * MSIZE,
                      out + (size_t)(b0 + 1) * MSIZE, P1, s_redF, t, 0);
    }
}

extern "C" void kernel_launch(void* const* d_in, const int* in_sizes, int n_in,
                              void* d_out, int out_size) {
    const float* memory = (const float*)d_in[0];
    const float* cs     = (const float*)d_in[1];
    const float* prev   = (const float*)d_in[2];
    const float* Wk     = (const float*)d_in[3];
    const float* Wb     = (const float*)d_in[4];
    const float* bb     = (const float*)d_in[5];
    const float* Wgate  = (const float*)d_in[6];
    const float* bgate  = (const float*)d_in[7];
    const float* Ws     = (const float*)d_in[8];
    const float* bs     = (const float*)d_in[9];
    const float* Wg     = (const float*)d_in[10];
    const float* bg     = (const float*)d_in[11];
    float* out = (float*)d_out;

    ntm_head_kernel<<<BATCH / 2, NTHREADS>>>(memory, cs, prev, Wk, Wb, bb,
                                             Wgate, bgate, Ws, bs, Wg, bg, out);
}